// round 12
// baseline (speedup 1.0000x reference)
#include <cuda_runtime.h>
#include <cuda_bf16.h>
#include <cstdint>

// ---------------------------------------------------------------------------
// LocalAttentionND. Round 9:
//  - all fp32->bf16 hi/lo conversion hoisted out of the GEMMs (weight prep
//    kernels + epilogue dual-writes); GEMM staging is pure byte copies.
//  - attention split into interior (no bounds checks) / border kernels.
// ---------------------------------------------------------------------------

static constexpr int NTOK = 8192;      // 2*64*64
static constexpr int CDIM = 256;
static constexpr int QKVN = 768;

__device__ float g_qkv[NTOK * QKVN];     // silu(x@W_qkv); q/k rewritten in-place
__device__ float g_wp[NTOK * 8];         // width[4], sharp[4] per token
__device__ float g_outn[NTOK * CDIM];    // rmsnorm(attention out)

// bf16 hi/lo operand buffers
__device__ __align__(16) __nv_bfloat16 g_xhi[NTOK * CDIM], g_xlo[NTOK * CDIM];
__device__ __align__(16) __nv_bfloat16 g_vhi[NTOK * CDIM], g_vlo[NTOK * CDIM];
__device__ __align__(16) __nv_bfloat16 g_mhi[NTOK * CDIM], g_mlo[NTOK * CDIM];
__device__ __align__(16) __nv_bfloat16 g_wqkv_hi[CDIM * QKVN], g_wqkv_lo[CDIM * QKVN];
__device__ __align__(16) __nv_bfloat16 g_wg_hi[CDIM * CDIM],  g_wg_lo[CDIM * CDIM];
__device__ __align__(16) __nv_bfloat16 g_wo_hi[CDIM * CDIM],  g_wo_lo[CDIM * CDIM];

__device__ __forceinline__ float fsig(float x)  { return 1.f / (1.f + __expf(-x)); }
__device__ __forceinline__ float fsilu(float x) { return x   / (1.f + __expf(-x)); }

// ---------------------------------------------------------------------------
// prep: fp32 -> bf16 hi/lo split
// ---------------------------------------------------------------------------
__global__ void convw_kernel(const float* __restrict__ src,
                             __nv_bfloat16* __restrict__ hi,
                             __nv_bfloat16* __restrict__ lo, int n)
{
    int i = blockIdx.x * blockDim.x + threadIdx.x;
    if (i >= n) return;
    float v = src[i];
    __nv_bfloat16 h = __float2bfloat16_rn(v);
    hi[i] = h;
    lo[i] = __float2bfloat16_rn(v - __bfloat162float(h));
}

__device__ __forceinline__ void st_hilo2(__nv_bfloat16* hp, __nv_bfloat16* lp,
                                         float a, float b)
{
    __nv_bfloat162 h, l;
    h.x = __float2bfloat16_rn(a); h.y = __float2bfloat16_rn(b);
    l.x = __float2bfloat16_rn(a - __bfloat162float(h.x));
    l.y = __float2bfloat16_rn(b - __bfloat162float(h.y));
    *(__nv_bfloat162*)hp = h;
    *(__nv_bfloat162*)lp = l;
}

// ---------------------------------------------------------------------------
// tensor-core helpers
// ---------------------------------------------------------------------------
__device__ __forceinline__ void ldsm_x4(uint32_t addr, uint32_t& r0, uint32_t& r1,
                                        uint32_t& r2, uint32_t& r3)
{
    asm volatile("ldmatrix.sync.aligned.m8n8.x4.shared.b16 {%0,%1,%2,%3}, [%4];"
                 : "=r"(r0), "=r"(r1), "=r"(r2), "=r"(r3) : "r"(addr));
}
__device__ __forceinline__ void ldsm_x4_t(uint32_t addr, uint32_t& r0, uint32_t& r1,
                                          uint32_t& r2, uint32_t& r3)
{
    asm volatile("ldmatrix.sync.aligned.m8n8.x4.trans.shared.b16 {%0,%1,%2,%3}, [%4];"
                 : "=r"(r0), "=r"(r1), "=r"(r2), "=r"(r3) : "r"(addr));
}
__device__ __forceinline__ void mma16816(float* c, const uint32_t* a,
                                         uint32_t b0, uint32_t b1)
{
    asm volatile(
        "mma.sync.aligned.m16n8k16.row.col.f32.bf16.bf16.f32 "
        "{%0,%1,%2,%3}, {%4,%5,%6,%7}, {%8,%9}, {%0,%1,%2,%3};"
        : "+f"(c[0]), "+f"(c[1]), "+f"(c[2]), "+f"(c[3])
        : "r"(a[0]), "r"(a[1]), "r"(a[2]), "r"(a[3]), "r"(b0), "r"(b1));
}

// ---------------------------------------------------------------------------
// GEMM on preconverted bf16 hi/lo operands. Tile 128x128x32, 256 thr, 8 warps,
// warp tile 64x32, 3-MMA split (hh + hl + lh). K = 256.
// EPI=0: silu -> fp32 Cout; optional bf16 dual-write (cols >= dcol0) to Dhi/Dlo.
// EPI=1: gate-merge; writes ONLY bf16 hi/lo to Dhi/Dlo (v32 = fp32 v source).
// ---------------------------------------------------------------------------
template <int EPI>
__global__ void __launch_bounds__(256) gemm_bf16t(
    const __nv_bfloat16* __restrict__ Ahi, const __nv_bfloat16* __restrict__ Alo, int lda,
    const __nv_bfloat16* __restrict__ Whi, const __nv_bfloat16* __restrict__ Wlo, int ldw,
    const float* __restrict__ bias,
    float* __restrict__ Cout, int ldc,
    __nv_bfloat16* __restrict__ Dhi, __nv_bfloat16* __restrict__ Dlo, int dcol0,
    const float* __restrict__ v32, int ldv,
    const float* __restrict__ outn)
{
    __shared__ __align__(16) __nv_bfloat16 As_hi[128][40];
    __shared__ __align__(16) __nv_bfloat16 As_lo[128][40];
    __shared__ __align__(16) __nv_bfloat16 Bs_hi[32][136];
    __shared__ __align__(16) __nv_bfloat16 Bs_lo[32][136];

    const int tid = threadIdx.x;
    const int warp = tid >> 5, lane = tid & 31;
    const int row0 = blockIdx.x * 128;
    const int col0 = blockIdx.y * 128;

    // staging: A thread covers row=tid>>1, k window (tid&1)*16 (16 bf16 = 2 uint4)
    const int sar = tid >> 1, sak = (tid & 1) * 16;
    // B thread covers k=tid>>3, n window (tid&7)*16
    const int sbk = tid >> 3, sbn = (tid & 7) * 16;
    const __nv_bfloat16* Aph = Ahi + (size_t)(row0 + sar) * lda + sak;
    const __nv_bfloat16* Apl = Alo + (size_t)(row0 + sar) * lda + sak;
    const __nv_bfloat16* Wph = Whi + (size_t)sbk * ldw + col0 + sbn;
    const __nv_bfloat16* Wpl = Wlo + (size_t)sbk * ldw + col0 + sbn;

    const int warpM = (warp >> 2) * 64;
    const int warpN = (warp & 3) * 32;
    const int qr = (lane & 7) + ((lane >> 3) & 1) * 8;
    const int qc = (lane >> 4) * 8;
    uint32_t aHi = (uint32_t)__cvta_generic_to_shared(&As_hi[warpM + qr][qc]);
    uint32_t aLo = (uint32_t)__cvta_generic_to_shared(&As_lo[warpM + qr][qc]);
    uint32_t bHi = (uint32_t)__cvta_generic_to_shared(&Bs_hi[qr][warpN + qc]);
    uint32_t bLo = (uint32_t)__cvta_generic_to_shared(&Bs_lo[qr][warpN + qc]);
    const uint32_t ArowB = 40 * 2;
    const uint32_t BrowB = 136 * 2;

    float acc[4][4][4] = {};

    // prologue prefetch
    uint4 pah[2], pal[2], pbh[2], pbl[2];
    pah[0] = ((const uint4*)Aph)[0]; pah[1] = ((const uint4*)Aph)[1];
    pal[0] = ((const uint4*)Apl)[0]; pal[1] = ((const uint4*)Apl)[1];
    pbh[0] = ((const uint4*)Wph)[0]; pbh[1] = ((const uint4*)Wph)[1];
    pbl[0] = ((const uint4*)Wpl)[0]; pbl[1] = ((const uint4*)Wpl)[1];

    for (int k0 = 0; k0 < 256; k0 += 32) {
        *(uint4*)&As_hi[sar][sak]     = pah[0];
        *(uint4*)&As_hi[sar][sak + 8] = pah[1];
        *(uint4*)&As_lo[sar][sak]     = pal[0];
        *(uint4*)&As_lo[sar][sak + 8] = pal[1];
        *(uint4*)&Bs_hi[sbk][sbn]     = pbh[0];
        *(uint4*)&Bs_hi[sbk][sbn + 8] = pbh[1];
        *(uint4*)&Bs_lo[sbk][sbn]     = pbl[0];
        *(uint4*)&Bs_lo[sbk][sbn + 8] = pbl[1];
        __syncthreads();

        if (k0 + 32 < 256) {
            const __nv_bfloat16* ah = Aph + k0 + 32;
            const __nv_bfloat16* al = Apl + k0 + 32;
            const __nv_bfloat16* bh = Wph + (size_t)(k0 + 32) * ldw;
            const __nv_bfloat16* bl = Wpl + (size_t)(k0 + 32) * ldw;
            pah[0] = ((const uint4*)ah)[0]; pah[1] = ((const uint4*)ah)[1];
            pal[0] = ((const uint4*)al)[0]; pal[1] = ((const uint4*)al)[1];
            pbh[0] = ((const uint4*)bh)[0]; pbh[1] = ((const uint4*)bh)[1];
            pbl[0] = ((const uint4*)bl)[0]; pbl[1] = ((const uint4*)bl)[1];
        }

#pragma unroll
        for (int ks = 0; ks < 2; ks++) {
            uint32_t ah[4][4], al[4][4];
#pragma unroll
            for (int i = 0; i < 4; i++) {
                uint32_t off = (uint32_t)(i * 16) * ArowB + ks * 32;
                ldsm_x4(aHi + off, ah[i][0], ah[i][1], ah[i][2], ah[i][3]);
                ldsm_x4(aLo + off, al[i][0], al[i][1], al[i][2], al[i][3]);
            }
            uint32_t bh[2][4], bl[2][4];
#pragma unroll
            for (int j2 = 0; j2 < 2; j2++) {
                uint32_t off = (uint32_t)(j2 * 16) * 2 + ks * 16 * BrowB;
                ldsm_x4_t(bHi + off, bh[j2][0], bh[j2][1], bh[j2][2], bh[j2][3]);
                ldsm_x4_t(bLo + off, bl[j2][0], bl[j2][1], bl[j2][2], bl[j2][3]);
            }
#pragma unroll
            for (int i = 0; i < 4; i++)
#pragma unroll
                for (int j = 0; j < 4; j++)
                    mma16816(acc[i][j], ah[i], bh[j >> 1][(j & 1) * 2], bh[j >> 1][(j & 1) * 2 + 1]);
#pragma unroll
            for (int i = 0; i < 4; i++)
#pragma unroll
                for (int j = 0; j < 4; j++)
                    mma16816(acc[i][j], ah[i], bl[j >> 1][(j & 1) * 2], bl[j >> 1][(j & 1) * 2 + 1]);
#pragma unroll
            for (int i = 0; i < 4; i++)
#pragma unroll
                for (int j = 0; j < 4; j++)
                    mma16816(acc[i][j], al[i], bh[j >> 1][(j & 1) * 2], bh[j >> 1][(j & 1) * 2 + 1]);
        }
        __syncthreads();
    }

    const int er = lane >> 2, ec = (lane & 3) * 2;
#pragma unroll
    for (int i = 0; i < 4; i++) {
        int r0 = row0 + warpM + i * 16 + er;
#pragma unroll
        for (int j = 0; j < 4; j++) {
            int c = col0 + warpN + j * 8 + ec;
#pragma unroll
            for (int h = 0; h < 2; h++) {
                int row = r0 + h * 8;
                float v0 = acc[i][j][h * 2], v1 = acc[i][j][h * 2 + 1];
                if (EPI == 0) {
                    float2 r;
                    r.x = fsilu(v0);
                    r.y = fsilu(v1);
                    *(float2*)(Cout + (size_t)row * ldc + c) = r;
                    if (Dhi && c >= dcol0) {
                        size_t off = (size_t)row * CDIM + (c - dcol0);
                        st_hilo2(Dhi + off, Dlo + off, r.x, r.y);
                    }
                } else {
                    float2 vv = *(const float2*)(v32 + (size_t)row * ldv + c);
                    float2 oo = *(const float2*)(outn + (size_t)row * CDIM + c);
                    float2 bb = *(const float2*)(bias + c);
                    float g, m0, m1;
                    g = fsig(fsilu(v0 + bb.x)); m0 = g * vv.x + (1.f - g) * oo.x;
                    g = fsig(fsilu(v1 + bb.y)); m1 = g * vv.y + (1.f - g) * oo.y;
                    size_t off = (size_t)row * CDIM + c;
                    st_hilo2(Dhi + off, Dlo + off, m0, m1);
                }
            }
        }
    }
}

// ---------------------------------------------------------------------------
// wp = silu(x @ W_wp + b_wp); width = sig(.)*maxd+0.5, sharp = sig(.)*9.5+0.5
// ---------------------------------------------------------------------------
__global__ void __launch_bounds__(256) wp_kernel(
    const float* __restrict__ x, const float* __restrict__ W_wp,
    const float* __restrict__ b_wp, float* __restrict__ wp_out)
{
    int warp = (blockIdx.x * blockDim.x + threadIdx.x) >> 5;
    int lane = threadIdx.x & 31;
    if (warp >= NTOK) return;
    const float* xr = x + (size_t)warp * CDIM;
    float acc[8] = {};
    for (int k = lane; k < CDIM; k += 32) {
        float xv = xr[k];
        const float* wr = W_wp + k * 8;
#pragma unroll
        for (int o = 0; o < 8; o++) acc[o] += xv * wr[o];
    }
#pragma unroll
    for (int o = 0; o < 8; o++)
#pragma unroll
        for (int off = 16; off; off >>= 1)
            acc[o] += __shfl_xor_sync(0xffffffffu, acc[o], off);
    if (lane < 8) {
        const float maxd = 4.242640687119285f;  // sqrt(18)
        float t = acc[lane] + b_wp[lane];
        float s = fsilu(t);
        float sg = fsig(s);
        wp_out[warp * 8 + lane] = (lane < 4) ? (sg * maxd + 0.5f) : (sg * 9.5f + 0.5f);
    }
}

// ---------------------------------------------------------------------------
// In-place rmsnorm (per head, D=64) + RoPE (position = head index) on q, k.
// ---------------------------------------------------------------------------
__global__ void __launch_bounds__(256) rmsrope_kernel(
    const float* __restrict__ w_qnorm, const float* __restrict__ w_knorm)
{
    int token = blockIdx.x;
    int warpId = threadIdx.x >> 5, lane = threadIdx.x & 31;
    int which = warpId >> 2;    // 0=q, 1=k
    int head  = warpId & 3;
    const float* wn = which ? w_knorm : w_qnorm;
    float* base = g_qkv + (size_t)token * QKVN + which * CDIM + head * 64;

    float x1 = base[lane], x2 = base[lane + 32];
    float ss = x1 * x1 + x2 * x2;
#pragma unroll
    for (int off = 16; off; off >>= 1) ss += __shfl_xor_sync(0xffffffffu, ss, off);
    float inv = rsqrtf(ss * (1.f / 64.f) + 1e-6f);
    x1 = x1 * inv * wn[lane];
    x2 = x2 * inv * wn[lane + 32];

    float freq = exp2f(-(float)lane * (13.287712379549449f / 32.f));  // log2(10000)/32
    float ang = (float)head * freq;
    float c = cosf(ang), s = sinf(ang);
    base[lane]      = x1 * c - x2 * s;
    base[lane + 32] = x1 * s + x2 * c;
}

// ---------------------------------------------------------------------------
// Attention, templated: MODE=0 interior (y,x in [3,60], no bounds checks),
// MODE=1 border (checked). 1 warp per (token, head), 2 tokens per block.
// ---------------------------------------------------------------------------
template <int MODE>
__global__ void __launch_bounds__(256) attn_kernel_t(const float* __restrict__ w_onorm)
{
    __shared__ __align__(16) float s_q[8][64];
    __shared__ float s_p[8][52];
    __shared__ float s_out[2][256];
    __shared__ float s_ss[2];
    __shared__ int   s_tok[2];

    const int warpId = threadIdx.x >> 5, lane = threadIdx.x & 31;
    const int tl = warpId >> 2;      // token-local 0/1
    const int head = warpId & 3;

    int token;
    if (MODE == 0) {
        int blk = blockIdx.x;                 // 2*58*29 = 3364 blocks
        int b = blk / 1682;                   // 58*29
        int rem = blk - b * 1682;
        int y = 3 + rem / 29;
        int x = 3 + 2 * (rem % 29) + tl;
        token = (b << 12) + (y << 6) + x;
    } else {
        int bi = blockIdx.x * 2 + tl;         // < 1464
        int b = bi / 732;
        int r = bi - b * 732;
        int y, x;
        if (r < 384) { int ry = r >> 6; y = (ry < 3) ? ry : 58 + ry; x = r & 63; }
        else { int r2 = r - 384; y = 3 + r2 / 6; int xi = r2 % 6; x = (xi < 3) ? xi : 58 + xi; }
        token = (b << 12) + (y << 6) + x;
    }
    const int b = token >> 12;
    const int y = (token >> 6) & 63, xx = token & 63;

    if (threadIdx.x < 2) s_ss[threadIdx.x] = 0.f;
    if (lane == 0 && head == 0) s_tok[tl] = token;

    const float* qrow = g_qkv + (size_t)token * QKVN + head * 64;
    s_q[warpId][lane]      = qrow[lane];
    s_q[warpId][lane + 32] = qrow[lane + 32];
    __syncwarp();

    const int sub = lane & 7;
    const int grp = lane >> 3;
    float4 q4a = ((const float4*)s_q[warpId])[sub];
    float4 q4b = ((const float4*)s_q[warpId])[sub + 8];

    const float width = g_wp[token * 8 + head];
    const float sharp = g_wp[token * 8 + 4 + head];
    const float* kbase = g_qkv + 256 + (size_t)head * 64;

#pragma unroll
    for (int r = 0; r < 13; r++) {
        int w = r * 4 + grp;
        bool act = (w < 49);
        int wc = act ? w : 48;
        int di = wc / 7 - 3, dj = wc % 7 - 3;
        int ny = y + di, nx = xx + dj;
        bool inb = (MODE == 0) ? true : (((unsigned)ny < 64u) & ((unsigned)nx < 64u));
        float part = 0.f;
        if (act & inb) {
            const float4* kr = (const float4*)(kbase +
                (size_t)((b << 12) + (ny << 6) + nx) * QKVN);
            float4 ka = kr[sub];
            float4 kb = kr[sub + 8];
            part = q4a.x * ka.x + q4a.y * ka.y + q4a.z * ka.z + q4a.w * ka.w
                 + q4b.x * kb.x + q4b.y * kb.y + q4b.z * kb.z + q4b.w * kb.w;
        }
        part += __shfl_xor_sync(0xffffffffu, part, 1);
        part += __shfl_xor_sync(0xffffffffu, part, 2);
        part += __shfl_xor_sync(0xffffffffu, part, 4);
        if (act && sub == 0) {
            float rd = sqrtf((float)(di * di + dj * dj));
            float mask = fsig((width - rd) * sharp);
            s_p[warpId][w] = part * 0.125f - (1.f - mask) * 10000.f;
        }
    }
    __syncwarp();

    float sc0 = s_p[warpId][lane];
    float sc1 = (lane + 32 < 49) ? s_p[warpId][lane + 32] : -1e30f;
    float mx = fmaxf(sc0, sc1);
#pragma unroll
    for (int off = 16; off; off >>= 1) mx = fmaxf(mx, __shfl_xor_sync(0xffffffffu, mx, off));
    float p0 = __expf(sc0 - mx);
    float p1 = __expf(sc1 - mx);
    float ds = p0 + p1;
#pragma unroll
    for (int off = 16; off; off >>= 1) ds += __shfl_xor_sync(0xffffffffu, ds, off);
    float rdm = 1.f / ds;
    s_p[warpId][lane] = p0 * rdm;
    if (lane + 32 < 49) s_p[warpId][lane + 32] = p1 * rdm;
    __syncwarp();

    float o0 = 0.f, o1 = 0.f;
    const float* vtok = g_qkv + (size_t)token * QKVN + 512 + head * 64;
#pragma unroll
    for (int ii = 0; ii < 7; ii++) {
        int ny = y + ii - 3;
        if (MODE == 1 && (unsigned)ny >= 64u) continue;
#pragma unroll
        for (int jj = 0; jj < 7; jj++) {
            int nx = xx + jj - 3;
            if (MODE == 1 && (unsigned)nx >= 64u) continue;
            float p = s_p[warpId][ii * 7 + jj];
            const float* vrow = vtok + (ptrdiff_t)((ii - 3) * 64 + (jj - 3)) * QKVN;
            o0 += p * vrow[lane];
            o1 += p * vrow[lane + 32];
        }
    }

    s_out[tl][head * 64 + lane]      = o0;
    s_out[tl][head * 64 + lane + 32] = o1;

    float pss = o0 * o0 + o1 * o1;
#pragma unroll
    for (int off = 16; off; off >>= 1) pss += __shfl_xor_sync(0xffffffffu, pss, off);
    __syncthreads();
    if (lane == 0) atomicAdd(&s_ss[tl], pss);
    __syncthreads();

    for (int e = threadIdx.x; e < 512; e += 256) {
        int t2 = e >> 8, c = e & 255;
        float rinv = rsqrtf(s_ss[t2] * (1.f / 256.f) + 1e-6f);
        g_outn[(size_t)s_tok[t2] * CDIM + c] = s_out[t2][c] * rinv * w_onorm[c];
    }
}

// ---------------------------------------------------------------------------
extern "C" void kernel_launch(void* const* d_in, const int* in_sizes, int n_in,
                              void* d_out, int out_size)
{
    const float* x       = (const float*)d_in[0];
    const float* W_qkv   = (const float*)d_in[1];
    const float* w_qnorm = (const float*)d_in[2];
    const float* w_knorm = (const float*)d_in[3];
    const float* W_wp    = (const float*)d_in[4];
    const float* b_wp    = (const float*)d_in[5];
    const float* w_onorm = (const float*)d_in[6];
    const float* W_out   = (const float*)d_in[7];
    const float* W_gate  = (const float*)d_in[8];
    const float* b_gate  = (const float*)d_in[9];
    float* out = (float*)d_out;

    float *p_qkv, *p_wp, *p_outn;
    cudaGetSymbolAddress((void**)&p_qkv, g_qkv);
    cudaGetSymbolAddress((void**)&p_wp, g_wp);
    cudaGetSymbolAddress((void**)&p_outn, g_outn);
    __nv_bfloat16 *p_xhi, *p_xlo, *p_vhi, *p_vlo, *p_mhi, *p_mlo;
    __nv_bfloat16 *p_wqh, *p_wql, *p_wgh, *p_wgl, *p_woh, *p_wol;
    cudaGetSymbolAddress((void**)&p_xhi, g_xhi); cudaGetSymbolAddress((void**)&p_xlo, g_xlo);
    cudaGetSymbolAddress((void**)&p_vhi, g_vhi); cudaGetSymbolAddress((void**)&p_vlo, g_vlo);
    cudaGetSymbolAddress((void**)&p_mhi, g_mhi); cudaGetSymbolAddress((void**)&p_mlo, g_mlo);
    cudaGetSymbolAddress((void**)&p_wqh, g_wqkv_hi); cudaGetSymbolAddress((void**)&p_wql, g_wqkv_lo);
    cudaGetSymbolAddress((void**)&p_wgh, g_wg_hi);   cudaGetSymbolAddress((void**)&p_wgl, g_wg_lo);
    cudaGetSymbolAddress((void**)&p_woh, g_wo_hi);   cudaGetSymbolAddress((void**)&p_wol, g_wo_lo);

    // 0. preconvert weights + x to bf16 hi/lo
    convw_kernel<<<(CDIM * QKVN + 255) / 256, 256>>>(W_qkv, p_wqh, p_wql, CDIM * QKVN);
    convw_kernel<<<(CDIM * CDIM + 255) / 256, 256>>>(W_gate, p_wgh, p_wgl, CDIM * CDIM);
    convw_kernel<<<(CDIM * CDIM + 255) / 256, 256>>>(W_out, p_woh, p_wol, CDIM * CDIM);
    convw_kernel<<<(NTOK * CDIM + 255) / 256, 256>>>(x, p_xhi, p_xlo, NTOK * CDIM);

    // 1. qkv = silu(x @ W_qkv): fp32 out + bf16 dual-write for v columns (>=512)
    gemm_bf16t<0><<<dim3(NTOK / 128, QKVN / 128), 256>>>(
        p_xhi, p_xlo, CDIM, p_wqh, p_wql, QKVN, nullptr,
        p_qkv, QKVN, p_vhi, p_vlo, 512, nullptr, 0, nullptr);
    // 2. width/sharpness projection
    wp_kernel<<<NTOK / 8, 256>>>(x, W_wp, b_wp, p_wp);
    // 3. rmsnorm + rope on q, k (in place)
    rmsrope_kernel<<<NTOK, 256>>>(w_qnorm, w_knorm);
    // 4. windowed attention + fused output rmsnorm (interior + border)
    attn_kernel_t<0><<<3364, 256>>>(w_onorm);
    attn_kernel_t<1><<<732, 256>>>(w_onorm);
    // 5. gate GEMM + merge epilogue -> bf16 hi/lo merged
    gemm_bf16t<1><<<dim3(NTOK / 128, CDIM / 128), 256>>>(
        p_vhi, p_vlo, CDIM, p_wgh, p_wgl, CDIM, b_gate,
        nullptr, 0, p_mhi, p_mlo, 0, p_qkv + 512, QKVN, p_outn);
    // 6. final: silu(merged @ W_out) -> fp32 out
    gemm_bf16t<0><<<dim3(NTOK / 128, CDIM / 128), 256>>>(
        p_mhi, p_mlo, CDIM, p_woh, p_wol, CDIM, nullptr,
        out, CDIM, nullptr, nullptr, 0, nullptr, 0, nullptr);
}

// round 14
// speedup vs baseline: 1.0104x; 1.0104x over previous
#include <cuda_runtime.h>
#include <cuda_bf16.h>
#include <cstdint>

// ---------------------------------------------------------------------------
// LocalAttentionND. Round 13:
//  - single merged prep kernel (weights + x -> bf16 hi/lo)
//  - attention: per-token rsqrt hoisted out of the 512-elem epilogue loop
//  - wp + rmsrope fused into one kernel (288 threads)
//  - GEMMs: bf16 hi/lo 3-MMA split tensor-core (round-9 form)
// ---------------------------------------------------------------------------

static constexpr int NTOK = 8192;      // 2*64*64
static constexpr int CDIM = 256;
static constexpr int QKVN = 768;

__device__ float g_qkv[NTOK * QKVN];     // silu(x@W_qkv); q/k rewritten in-place
__device__ float g_wp[NTOK * 8];         // width[4], sharp[4] per token
__device__ float g_outn[NTOK * CDIM];    // rmsnorm(attention out)

// bf16 hi/lo operand buffers
__device__ __align__(16) __nv_bfloat16 g_xhi[NTOK * CDIM], g_xlo[NTOK * CDIM];
__device__ __align__(16) __nv_bfloat16 g_vhi[NTOK * CDIM], g_vlo[NTOK * CDIM];
__device__ __align__(16) __nv_bfloat16 g_mhi[NTOK * CDIM], g_mlo[NTOK * CDIM];
__device__ __align__(16) __nv_bfloat16 g_wqkv_hi[CDIM * QKVN], g_wqkv_lo[CDIM * QKVN];
__device__ __align__(16) __nv_bfloat16 g_wg_hi[CDIM * CDIM],  g_wg_lo[CDIM * CDIM];
__device__ __align__(16) __nv_bfloat16 g_wo_hi[CDIM * CDIM],  g_wo_lo[CDIM * CDIM];

__device__ __forceinline__ float fsig(float x)  { return 1.f / (1.f + __expf(-x)); }
__device__ __forceinline__ float fsilu(float x) { return x   / (1.f + __expf(-x)); }

// ---------------------------------------------------------------------------
// prep: one kernel converts all fp32 operands to bf16 hi/lo
// segments: W_qkv | W_gate | W_out | x
// ---------------------------------------------------------------------------
__global__ void prep_kernel(const float* __restrict__ W_qkv,
                            const float* __restrict__ W_gate,
                            const float* __restrict__ W_out,
                            const float* __restrict__ x)
{
    const int n0 = CDIM * QKVN;           // 196608
    const int n1 = n0 + CDIM * CDIM;      // 327680
    const int n2 = n1 + CDIM * CDIM;      // 458752
    const int n3 = n2 + NTOK * CDIM;      // 2555904
    int i = blockIdx.x * blockDim.x + threadIdx.x;
    if (i >= n3) return;
    const float* src;
    __nv_bfloat16 *hi, *lo;
    int j;
    if (i < n0)      { src = W_qkv;  hi = g_wqkv_hi; lo = g_wqkv_lo; j = i; }
    else if (i < n1) { src = W_gate; hi = g_wg_hi;   lo = g_wg_lo;   j = i - n0; }
    else if (i < n2) { src = W_out;  hi = g_wo_hi;   lo = g_wo_lo;   j = i - n1; }
    else             { src = x;      hi = g_xhi;     lo = g_xlo;     j = i - n2; }
    float v = src[j];
    __nv_bfloat16 h = __float2bfloat16_rn(v);
    hi[j] = h;
    lo[j] = __float2bfloat16_rn(v - __bfloat162float(h));
}

__device__ __forceinline__ void st_hilo2(__nv_bfloat16* hp, __nv_bfloat16* lp,
                                         float a, float b)
{
    __nv_bfloat162 h, l;
    h.x = __float2bfloat16_rn(a); h.y = __float2bfloat16_rn(b);
    l.x = __float2bfloat16_rn(a - __bfloat162float(h.x));
    l.y = __float2bfloat16_rn(b - __bfloat162float(h.y));
    *(__nv_bfloat162*)hp = h;
    *(__nv_bfloat162*)lp = l;
}

// ---------------------------------------------------------------------------
// tensor-core helpers
// ---------------------------------------------------------------------------
__device__ __forceinline__ void ldsm_x4(uint32_t addr, uint32_t& r0, uint32_t& r1,
                                        uint32_t& r2, uint32_t& r3)
{
    asm volatile("ldmatrix.sync.aligned.m8n8.x4.shared.b16 {%0,%1,%2,%3}, [%4];"
                 : "=r"(r0), "=r"(r1), "=r"(r2), "=r"(r3) : "r"(addr));
}
__device__ __forceinline__ void ldsm_x4_t(uint32_t addr, uint32_t& r0, uint32_t& r1,
                                          uint32_t& r2, uint32_t& r3)
{
    asm volatile("ldmatrix.sync.aligned.m8n8.x4.trans.shared.b16 {%0,%1,%2,%3}, [%4];"
                 : "=r"(r0), "=r"(r1), "=r"(r2), "=r"(r3) : "r"(addr));
}
__device__ __forceinline__ void mma16816(float* c, const uint32_t* a,
                                         uint32_t b0, uint32_t b1)
{
    asm volatile(
        "mma.sync.aligned.m16n8k16.row.col.f32.bf16.bf16.f32 "
        "{%0,%1,%2,%3}, {%4,%5,%6,%7}, {%8,%9}, {%0,%1,%2,%3};"
        : "+f"(c[0]), "+f"(c[1]), "+f"(c[2]), "+f"(c[3])
        : "r"(a[0]), "r"(a[1]), "r"(a[2]), "r"(a[3]), "r"(b0), "r"(b1));
}

// ---------------------------------------------------------------------------
// GEMM on preconverted bf16 hi/lo operands. Tile 128x128x32, 256 thr, 8 warps,
// warp tile 64x32, 3-MMA split (hh + hl + lh). K = 256.
// EPI=0: silu -> fp32 Cout; optional bf16 dual-write (cols >= dcol0) to Dhi/Dlo.
// EPI=1: gate-merge; writes ONLY bf16 hi/lo to Dhi/Dlo (v32 = fp32 v source).
// ---------------------------------------------------------------------------
template <int EPI>
__global__ void __launch_bounds__(256) gemm_bf16t(
    const __nv_bfloat16* __restrict__ Ahi, const __nv_bfloat16* __restrict__ Alo, int lda,
    const __nv_bfloat16* __restrict__ Whi, const __nv_bfloat16* __restrict__ Wlo, int ldw,
    const float* __restrict__ bias,
    float* __restrict__ Cout, int ldc,
    __nv_bfloat16* __restrict__ Dhi, __nv_bfloat16* __restrict__ Dlo, int dcol0,
    const float* __restrict__ v32, int ldv,
    const float* __restrict__ outn)
{
    __shared__ __align__(16) __nv_bfloat16 As_hi[128][40];
    __shared__ __align__(16) __nv_bfloat16 As_lo[128][40];
    __shared__ __align__(16) __nv_bfloat16 Bs_hi[32][136];
    __shared__ __align__(16) __nv_bfloat16 Bs_lo[32][136];

    const int tid = threadIdx.x;
    const int warp = tid >> 5, lane = tid & 31;
    const int row0 = blockIdx.x * 128;
    const int col0 = blockIdx.y * 128;

    const int sar = tid >> 1, sak = (tid & 1) * 16;
    const int sbk = tid >> 3, sbn = (tid & 7) * 16;
    const __nv_bfloat16* Aph = Ahi + (size_t)(row0 + sar) * lda + sak;
    const __nv_bfloat16* Apl = Alo + (size_t)(row0 + sar) * lda + sak;
    const __nv_bfloat16* Wph = Whi + (size_t)sbk * ldw + col0 + sbn;
    const __nv_bfloat16* Wpl = Wlo + (size_t)sbk * ldw + col0 + sbn;

    const int warpM = (warp >> 2) * 64;
    const int warpN = (warp & 3) * 32;
    const int qr = (lane & 7) + ((lane >> 3) & 1) * 8;
    const int qc = (lane >> 4) * 8;
    uint32_t aHi = (uint32_t)__cvta_generic_to_shared(&As_hi[warpM + qr][qc]);
    uint32_t aLo = (uint32_t)__cvta_generic_to_shared(&As_lo[warpM + qr][qc]);
    uint32_t bHi = (uint32_t)__cvta_generic_to_shared(&Bs_hi[qr][warpN + qc]);
    uint32_t bLo = (uint32_t)__cvta_generic_to_shared(&Bs_lo[qr][warpN + qc]);
    const uint32_t ArowB = 40 * 2;
    const uint32_t BrowB = 136 * 2;

    float acc[4][4][4] = {};

    uint4 pah[2], pal[2], pbh[2], pbl[2];
    pah[0] = ((const uint4*)Aph)[0]; pah[1] = ((const uint4*)Aph)[1];
    pal[0] = ((const uint4*)Apl)[0]; pal[1] = ((const uint4*)Apl)[1];
    pbh[0] = ((const uint4*)Wph)[0]; pbh[1] = ((const uint4*)Wph)[1];
    pbl[0] = ((const uint4*)Wpl)[0]; pbl[1] = ((const uint4*)Wpl)[1];

    for (int k0 = 0; k0 < 256; k0 += 32) {
        *(uint4*)&As_hi[sar][sak]     = pah[0];
        *(uint4*)&As_hi[sar][sak + 8] = pah[1];
        *(uint4*)&As_lo[sar][sak]     = pal[0];
        *(uint4*)&As_lo[sar][sak + 8] = pal[1];
        *(uint4*)&Bs_hi[sbk][sbn]     = pbh[0];
        *(uint4*)&Bs_hi[sbk][sbn + 8] = pbh[1];
        *(uint4*)&Bs_lo[sbk][sbn]     = pbl[0];
        *(uint4*)&Bs_lo[sbk][sbn + 8] = pbl[1];
        __syncthreads();

        if (k0 + 32 < 256) {
            const __nv_bfloat16* ah = Aph + k0 + 32;
            const __nv_bfloat16* al = Apl + k0 + 32;
            const __nv_bfloat16* bh = Wph + (size_t)(k0 + 32) * ldw;
            const __nv_bfloat16* bl = Wpl + (size_t)(k0 + 32) * ldw;
            pah[0] = ((const uint4*)ah)[0]; pah[1] = ((const uint4*)ah)[1];
            pal[0] = ((const uint4*)al)[0]; pal[1] = ((const uint4*)al)[1];
            pbh[0] = ((const uint4*)bh)[0]; pbh[1] = ((const uint4*)bh)[1];
            pbl[0] = ((const uint4*)bl)[0]; pbl[1] = ((const uint4*)bl)[1];
        }

#pragma unroll
        for (int ks = 0; ks < 2; ks++) {
            uint32_t ah[4][4], al[4][4];
#pragma unroll
            for (int i = 0; i < 4; i++) {
                uint32_t off = (uint32_t)(i * 16) * ArowB + ks * 32;
                ldsm_x4(aHi + off, ah[i][0], ah[i][1], ah[i][2], ah[i][3]);
                ldsm_x4(aLo + off, al[i][0], al[i][1], al[i][2], al[i][3]);
            }
            uint32_t bh[2][4], bl[2][4];
#pragma unroll
            for (int j2 = 0; j2 < 2; j2++) {
                uint32_t off = (uint32_t)(j2 * 16) * 2 + ks * 16 * BrowB;
                ldsm_x4_t(bHi + off, bh[j2][0], bh[j2][1], bh[j2][2], bh[j2][3]);
                ldsm_x4_t(bLo + off, bl[j2][0], bl[j2][1], bl[j2][2], bl[j2][3]);
            }
#pragma unroll
            for (int i = 0; i < 4; i++)
#pragma unroll
                for (int j = 0; j < 4; j++)
                    mma16816(acc[i][j], ah[i], bh[j >> 1][(j & 1) * 2], bh[j >> 1][(j & 1) * 2 + 1]);
#pragma unroll
            for (int i = 0; i < 4; i++)
#pragma unroll
                for (int j = 0; j < 4; j++)
                    mma16816(acc[i][j], ah[i], bl[j >> 1][(j & 1) * 2], bl[j >> 1][(j & 1) * 2 + 1]);
#pragma unroll
            for (int i = 0; i < 4; i++)
#pragma unroll
                for (int j = 0; j < 4; j++)
                    mma16816(acc[i][j], al[i], bh[j >> 1][(j & 1) * 2], bh[j >> 1][(j & 1) * 2 + 1]);
        }
        __syncthreads();
    }

    const int er = lane >> 2, ec = (lane & 3) * 2;
#pragma unroll
    for (int i = 0; i < 4; i++) {
        int r0 = row0 + warpM + i * 16 + er;
#pragma unroll
        for (int j = 0; j < 4; j++) {
            int c = col0 + warpN + j * 8 + ec;
#pragma unroll
            for (int h = 0; h < 2; h++) {
                int row = r0 + h * 8;
                float v0 = acc[i][j][h * 2], v1 = acc[i][j][h * 2 + 1];
                if (EPI == 0) {
                    float2 r;
                    r.x = fsilu(v0);
                    r.y = fsilu(v1);
                    *(float2*)(Cout + (size_t)row * ldc + c) = r;
                    if (Dhi && c >= dcol0) {
                        size_t off = (size_t)row * CDIM + (c - dcol0);
                        st_hilo2(Dhi + off, Dlo + off, r.x, r.y);
                    }
                } else {
                    float2 vv = *(const float2*)(v32 + (size_t)row * ldv + c);
                    float2 oo = *(const float2*)(outn + (size_t)row * CDIM + c);
                    float2 bb = *(const float2*)(bias + c);
                    float g, m0, m1;
                    g = fsig(fsilu(v0 + bb.x)); m0 = g * vv.x + (1.f - g) * oo.x;
                    g = fsig(fsilu(v1 + bb.y)); m1 = g * vv.y + (1.f - g) * oo.y;
                    size_t off = (size_t)row * CDIM + c;
                    st_hilo2(Dhi + off, Dlo + off, m0, m1);
                }
            }
        }
    }
}

// ---------------------------------------------------------------------------
// Fused per-token kernel, 288 threads, 1 block per token:
//  warps 0-7: in-place rmsnorm (per head, D=64) + RoPE (pos = head idx) on q,k
//  warp 8:    wp projection (width/sharpness, fused transforms)
// Independent data paths; no cross-warp sync needed.
// ---------------------------------------------------------------------------
__global__ void __launch_bounds__(288) fused_norm_wp_kernel(
    const float* __restrict__ w_qnorm, const float* __restrict__ w_knorm,
    const float* __restrict__ x, const float* __restrict__ W_wp,
    const float* __restrict__ b_wp, float* __restrict__ wp_out)
{
    int token = blockIdx.x;
    int warpId = threadIdx.x >> 5, lane = threadIdx.x & 31;

    if (warpId < 8) {
        int which = warpId >> 2;    // 0=q, 1=k
        int head  = warpId & 3;
        const float* wn = which ? w_knorm : w_qnorm;
        float* base = g_qkv + (size_t)token * QKVN + which * CDIM + head * 64;

        float x1 = base[lane], x2 = base[lane + 32];
        float ss = x1 * x1 + x2 * x2;
#pragma unroll
        for (int off = 16; off; off >>= 1) ss += __shfl_xor_sync(0xffffffffu, ss, off);
        float inv = rsqrtf(ss * (1.f / 64.f) + 1e-6f);
        x1 = x1 * inv * wn[lane];
        x2 = x2 * inv * wn[lane + 32];

        float freq = exp2f(-(float)lane * (13.287712379549449f / 32.f));
        float ang = (float)head * freq;
        float c = cosf(ang), s = sinf(ang);
        base[lane]      = x1 * c - x2 * s;
        base[lane + 32] = x1 * s + x2 * c;
    } else {
        const float* xr = x + (size_t)token * CDIM;
        float acc[8] = {};
        for (int k = lane; k < CDIM; k += 32) {
            float xv = xr[k];
            const float* wr = W_wp + k * 8;
#pragma unroll
            for (int o = 0; o < 8; o++) acc[o] += xv * wr[o];
        }
#pragma unroll
        for (int o = 0; o < 8; o++)
#pragma unroll
            for (int off = 16; off; off >>= 1)
                acc[o] += __shfl_xor_sync(0xffffffffu, acc[o], off);
        if (lane < 8) {
            const float maxd = 4.242640687119285f;  // sqrt(18)
            float t = acc[lane] + b_wp[lane];
            float s = fsilu(t);
            float sg = fsig(s);
            wp_out[token * 8 + lane] = (lane < 4) ? (sg * maxd + 0.5f) : (sg * 9.5f + 0.5f);
        }
    }
}

// ---------------------------------------------------------------------------
// Attention, templated: MODE=0 interior (y,x in [3,60], no bounds checks),
// MODE=1 border (checked). 1 warp per (token, head), 2 tokens per block.
// Per-token rsqrt hoisted to 2 threads (was per-element: 512 MUFU.RSQ/block).
// ---------------------------------------------------------------------------
template <int MODE>
__global__ void __launch_bounds__(256) attn_kernel_t(const float* __restrict__ w_onorm)
{
    __shared__ __align__(16) float s_q[8][64];
    __shared__ float s_p[8][52];
    __shared__ float s_out[2][256];
    __shared__ float s_ss[2];
    __shared__ float s_rinv[2];
    __shared__ int   s_tok[2];

    const int warpId = threadIdx.x >> 5, lane = threadIdx.x & 31;
    const int tl = warpId >> 2;
    const int head = warpId & 3;

    int token;
    if (MODE == 0) {
        int blk = blockIdx.x;                 // 2*58*29 = 3364 blocks
        int b = blk / 1682;
        int rem = blk - b * 1682;
        int y = 3 + rem / 29;
        int x = 3 + 2 * (rem % 29) + tl;
        token = (b << 12) + (y << 6) + x;
    } else {
        int bi = blockIdx.x * 2 + tl;         // < 1464
        int b = bi / 732;
        int r = bi - b * 732;
        int y, x;
        if (r < 384) { int ry = r >> 6; y = (ry < 3) ? ry : 58 + ry; x = r & 63; }
        else { int r2 = r - 384; y = 3 + r2 / 6; int xi = r2 % 6; x = (xi < 3) ? xi : 58 + xi; }
        token = (b << 12) + (y << 6) + x;
    }
    const int b = token >> 12;
    const int y = (token >> 6) & 63, xx = token & 63;

    if (threadIdx.x < 2) s_ss[threadIdx.x] = 0.f;
    if (lane == 0 && head == 0) s_tok[tl] = token;

    const float* qrow = g_qkv + (size_t)token * QKVN + head * 64;
    s_q[warpId][lane]      = qrow[lane];
    s_q[warpId][lane + 32] = qrow[lane + 32];
    __syncwarp();

    const int sub = lane & 7;
    const int grp = lane >> 3;
    float4 q4a = ((const float4*)s_q[warpId])[sub];
    float4 q4b = ((const float4*)s_q[warpId])[sub + 8];

    const float width = g_wp[token * 8 + head];
    const float sharp = g_wp[token * 8 + 4 + head];
    const float* kbase = g_qkv + 256 + (size_t)head * 64;

#pragma unroll
    for (int r = 0; r < 13; r++) {
        int w = r * 4 + grp;
        bool act = (w < 49);
        int wc = act ? w : 48;
        int di = wc / 7 - 3, dj = wc % 7 - 3;
        int ny = y + di, nx = xx + dj;
        bool inb = (MODE == 0) ? true : (((unsigned)ny < 64u) & ((unsigned)nx < 64u));
        float part = 0.f;
        if (act & inb) {
            const float4* kr = (const float4*)(kbase +
                (size_t)((b << 12) + (ny << 6) + nx) * QKVN);
            float4 ka = kr[sub];
            float4 kb = kr[sub + 8];
            part = q4a.x * ka.x + q4a.y * ka.y + q4a.z * ka.z + q4a.w * ka.w
                 + q4b.x * kb.x + q4b.y * kb.y + q4b.z * kb.z + q4b.w * kb.w;
        }
        part += __shfl_xor_sync(0xffffffffu, part, 1);
        part += __shfl_xor_sync(0xffffffffu, part, 2);
        part += __shfl_xor_sync(0xffffffffu, part, 4);
        if (act && sub == 0) {
            float rd = sqrtf((float)(di * di + dj * dj));
            float mask = fsig((width - rd) * sharp);
            s_p[warpId][w] = part * 0.125f - (1.f - mask) * 10000.f;
        }
    }
    __syncwarp();

    float sc0 = s_p[warpId][lane];
    float sc1 = (lane + 32 < 49) ? s_p[warpId][lane + 32] : -1e30f;
    float mx = fmaxf(sc0, sc1);
#pragma unroll
    for (int off = 16; off; off >>= 1) mx = fmaxf(mx, __shfl_xor_sync(0xffffffffu, mx, off));
    float p0 = __expf(sc0 - mx);
    float p1 = __expf(sc1 - mx);
    float ds = p0 + p1;
#pragma unroll
    for (int off = 16; off; off >>= 1) ds += __shfl_xor_sync(0xffffffffu, ds, off);
    float rdm = 1.f / ds;
    s_p[warpId][lane] = p0 * rdm;
    if (lane + 32 < 49) s_p[warpId][lane + 32] = p1 * rdm;
    __syncwarp();

    float o0 = 0.f, o1 = 0.f;
    const float* vtok = g_qkv + (size_t)token * QKVN + 512 + head * 64;
#pragma unroll
    for (int ii = 0; ii < 7; ii++) {
        int ny = y + ii - 3;
        if (MODE == 1 && (unsigned)ny >= 64u) continue;
#pragma unroll
        for (int jj = 0; jj < 7; jj++) {
            int nx = xx + jj - 3;
            if (MODE == 1 && (unsigned)nx >= 64u) continue;
            float p = s_p[warpId][ii * 7 + jj];
            const float* vrow = vtok + (ptrdiff_t)((ii - 3) * 64 + (jj - 3)) * QKVN;
            o0 += p * vrow[lane];
            o1 += p * vrow[lane + 32];
        }
    }

    s_out[tl][head * 64 + lane]      = o0;
    s_out[tl][head * 64 + lane + 32] = o1;

    float pss = o0 * o0 + o1 * o1;
#pragma unroll
    for (int off = 16; off; off >>= 1) pss += __shfl_xor_sync(0xffffffffu, pss, off);
    __syncthreads();
    if (lane == 0) atomicAdd(&s_ss[tl], pss);
    __syncthreads();
    if (threadIdx.x < 2)
        s_rinv[threadIdx.x] = rsqrtf(s_ss[threadIdx.x] * (1.f / 256.f) + 1e-6f);
    __syncthreads();

    for (int e = threadIdx.x; e < 512; e += 256) {
        int t2 = e >> 8, c = e & 255;
        g_outn[(size_t)s_tok[t2] * CDIM + c] = s_out[t2][c] * s_rinv[t2] * w_onorm[c];
    }
}

// ---------------------------------------------------------------------------
extern "C" void kernel_launch(void* const* d_in, const int* in_sizes, int n_in,
                              void* d_out, int out_size)
{
    const float* x       = (const float*)d_in[0];
    const float* W_qkv   = (const float*)d_in[1];
    const float* w_qnorm = (const float*)d_in[2];
    const float* w_knorm = (const float*)d_in[3];
    const float* W_wp    = (const float*)d_in[4];
    const float* b_wp    = (const float*)d_in[5];
    const float* w_onorm = (const float*)d_in[6];
    const float* W_out   = (const float*)d_in[7];
    const float* W_gate  = (const float*)d_in[8];
    const float* b_gate  = (const float*)d_in[9];
    float* out = (float*)d_out;

    float *p_qkv, *p_wp, *p_outn;
    cudaGetSymbolAddress((void**)&p_qkv, g_qkv);
    cudaGetSymbolAddress((void**)&p_wp, g_wp);
    cudaGetSymbolAddress((void**)&p_outn, g_outn);
    __nv_bfloat16 *p_xhi, *p_xlo, *p_vhi, *p_vlo, *p_mhi, *p_mlo;
    __nv_bfloat16 *p_wqh, *p_wql, *p_wgh, *p_wgl, *p_woh, *p_wol;
    cudaGetSymbolAddress((void**)&p_xhi, g_xhi); cudaGetSymbolAddress((void**)&p_xlo, g_xlo);
    cudaGetSymbolAddress((void**)&p_vhi, g_vhi); cudaGetSymbolAddress((void**)&p_vlo, g_vlo);
    cudaGetSymbolAddress((void**)&p_mhi, g_mhi); cudaGetSymbolAddress((void**)&p_mlo, g_mlo);
    cudaGetSymbolAddress((void**)&p_wqh, g_wqkv_hi); cudaGetSymbolAddress((void**)&p_wql, g_wqkv_lo);
    cudaGetSymbolAddress((void**)&p_wgh, g_wg_hi);   cudaGetSymbolAddress((void**)&p_wgl, g_wg_lo);
    cudaGetSymbolAddress((void**)&p_woh, g_wo_hi);   cudaGetSymbolAddress((void**)&p_wol, g_wo_lo);

    // 0. single merged prep: weights + x -> bf16 hi/lo
    const int NPREP = CDIM * QKVN + 2 * CDIM * CDIM + NTOK * CDIM;
    prep_kernel<<<(NPREP + 255) / 256, 256>>>(W_qkv, W_gate, W_out, x);

    // 1. qkv = silu(x @ W_qkv): fp32 out + bf16 dual-write for v columns (>=512)
    gemm_bf16t<0><<<dim3(NTOK / 128, QKVN / 128), 256>>>(
        p_xhi, p_xlo, CDIM, p_wqh, p_wql, QKVN, nullptr,
        p_qkv, QKVN, p_vhi, p_vlo, 512, nullptr, 0, nullptr);
    // 2+3. fused: rmsnorm+rope on q,k  |  width/sharpness projection
    fused_norm_wp_kernel<<<NTOK, 288>>>(w_qnorm, w_knorm, x, W_wp, b_wp, p_wp);
    // 4. windowed attention + fused output rmsnorm (interior + border)
    attn_kernel_t<0><<<3364, 256>>>(w_onorm);
    attn_kernel_t<1><<<732, 256>>>(w_onorm);
    // 5. gate GEMM + merge epilogue -> bf16 hi/lo merged
    gemm_bf16t<1><<<dim3(NTOK / 128, CDIM / 128), 256>>>(
        p_vhi, p_vlo, CDIM, p_wgh, p_wgl, CDIM, b_gate,
        nullptr, 0, p_mhi, p_mlo, 0, p_qkv + 512, QKVN, p_outn);
    // 6. final: silu(merged @ W_out) -> fp32 out
    gemm_bf16t<0><<<dim3(NTOK / 128, CDIM / 128), 256>>>(
        p_mhi, p_mlo, CDIM, p_woh, p_wol, CDIM, nullptr,
        out, CDIM, nullptr, nullptr, 0, nullptr, 0, nullptr);
}

// round 16
// speedup vs baseline: 1.0778x; 1.0667x over previous
#include <cuda_runtime.h>
#include <cuda_bf16.h>
#include <cstdint>

// ---------------------------------------------------------------------------
// LocalAttentionND. Round 15 (tcgen05 unavailable: harness PTX stage targets
// compute_103 without the 'a' feature suffix — mma.sync is the tensor path).
// Composition of measured-best pieces:
//  - R8 GEMM (bf16 hi/lo 3-MMA split, in-kernel A conversion) + weights
//    preconverted ONCE by a small prep kernel (B staging = pure copies).
//  - Attention: single launch, interior (uncheked) / border (checked) split,
//    per-token rsqrt hoisted.
//  - fused rmsnorm+rope + wp kernel.
// ---------------------------------------------------------------------------

static constexpr int NTOK = 8192;      // 2*64*64
static constexpr int CDIM = 256;
static constexpr int QKVN = 768;

__device__ float g_qkv[NTOK * QKVN];     // silu(x@W_qkv); q/k rewritten in-place
__device__ float g_wp[NTOK * 8];         // width[4], sharp[4] per token
__device__ float g_outn[NTOK * CDIM];    // rmsnorm(attention out)
__device__ float g_merged[NTOK * CDIM];  // gate*v + (1-gate)*outn

// preconverted weights (original [K][N] layout), bf16 hi/lo
__device__ __align__(16) __nv_bfloat16 g_wq_hi[CDIM * QKVN], g_wq_lo[CDIM * QKVN];
__device__ __align__(16) __nv_bfloat16 g_wg_hi[CDIM * CDIM], g_wg_lo[CDIM * CDIM];
__device__ __align__(16) __nv_bfloat16 g_wo_hi[CDIM * CDIM], g_wo_lo[CDIM * CDIM];

__device__ __forceinline__ float fsig(float x)  { return 1.f / (1.f + __expf(-x)); }
__device__ __forceinline__ float fsilu(float x) { return x   / (1.f + __expf(-x)); }

// ---------------------------------------------------------------------------
// prep: weights only -> bf16 hi/lo (one pass; ~459K elements)
// ---------------------------------------------------------------------------
__global__ void prep_w_kernel(const float* __restrict__ W_qkv,
                              const float* __restrict__ W_gate,
                              const float* __restrict__ W_out)
{
    const int n0 = CDIM * QKVN;           // 196608
    const int n1 = n0 + CDIM * CDIM;      // 262144 more
    const int n2 = n1 + CDIM * CDIM;
    int i = blockIdx.x * blockDim.x + threadIdx.x;
    if (i >= n2) return;
    const float* src;
    __nv_bfloat16 *hi, *lo;
    int j;
    if (i < n0)      { src = W_qkv;  hi = g_wq_hi; lo = g_wq_lo; j = i; }
    else if (i < n1) { src = W_gate; hi = g_wg_hi; lo = g_wg_lo; j = i - n0; }
    else             { src = W_out;  hi = g_wo_hi; lo = g_wo_lo; j = i - n1; }
    float v = src[j];
    __nv_bfloat16 h = __float2bfloat16_rn(v);
    hi[j] = h;
    lo[j] = __float2bfloat16_rn(v - __bfloat162float(h));
}

// convert float4 -> 4 bf16 hi + 4 bf16 lo (smem staging)
__device__ __forceinline__ void store_hilo(__nv_bfloat16* hp, __nv_bfloat16* lp, float4 v)
{
    __nv_bfloat162 h0, h1, l0, l1;
    h0.x = __float2bfloat16_rn(v.x); h0.y = __float2bfloat16_rn(v.y);
    h1.x = __float2bfloat16_rn(v.z); h1.y = __float2bfloat16_rn(v.w);
    l0.x = __float2bfloat16_rn(v.x - __bfloat162float(h0.x));
    l0.y = __float2bfloat16_rn(v.y - __bfloat162float(h0.y));
    l1.x = __float2bfloat16_rn(v.z - __bfloat162float(h1.x));
    l1.y = __float2bfloat16_rn(v.w - __bfloat162float(h1.y));
    *(__nv_bfloat162*)(hp)     = h0;
    *(__nv_bfloat162*)(hp + 2) = h1;
    *(__nv_bfloat162*)(lp)     = l0;
    *(__nv_bfloat162*)(lp + 2) = l1;
}

// ---------------------------------------------------------------------------
// tensor-core helpers (mma.sync path)
// ---------------------------------------------------------------------------
__device__ __forceinline__ void ldsm_x4(uint32_t addr, uint32_t& r0, uint32_t& r1,
                                        uint32_t& r2, uint32_t& r3)
{
    asm volatile("ldmatrix.sync.aligned.m8n8.x4.shared.b16 {%0,%1,%2,%3}, [%4];"
                 : "=r"(r0), "=r"(r1), "=r"(r2), "=r"(r3) : "r"(addr));
}
__device__ __forceinline__ void ldsm_x4_t(uint32_t addr, uint32_t& r0, uint32_t& r1,
                                          uint32_t& r2, uint32_t& r3)
{
    asm volatile("ldmatrix.sync.aligned.m8n8.x4.trans.shared.b16 {%0,%1,%2,%3}, [%4];"
                 : "=r"(r0), "=r"(r1), "=r"(r2), "=r"(r3) : "r"(addr));
}
__device__ __forceinline__ void mma16816(float* c, const uint32_t* a,
                                         uint32_t b0, uint32_t b1)
{
    asm volatile(
        "mma.sync.aligned.m16n8k16.row.col.f32.bf16.bf16.f32 "
        "{%0,%1,%2,%3}, {%4,%5,%6,%7}, {%8,%9}, {%0,%1,%2,%3};"
        : "+f"(c[0]), "+f"(c[1]), "+f"(c[2]), "+f"(c[3])
        : "r"(a[0]), "r"(a[1]), "r"(a[2]), "r"(a[3]), "r"(b0), "r"(b1));
}

// ---------------------------------------------------------------------------
// GEMM: Cout = epi(A[M,256] @ W[256,N] (+bias)). A fp32 (converted in-kernel),
// W preconverted bf16 hi/lo. Tile 128x128x32, 256 thr, 8 warps, warp 64x32,
// 3-MMA split (hh + hl + lh). K = 256.
// EPI=0: silu -> fp32. EPI=1: gate-merge (A is v; outn blended) -> fp32.
// ---------------------------------------------------------------------------
template <int EPI>
__global__ void __launch_bounds__(256) gemm_bf16s(
    const float* __restrict__ A, int lda,
    const __nv_bfloat16* __restrict__ Whi, const __nv_bfloat16* __restrict__ Wlo, int ldw,
    const float* __restrict__ bias,
    float* __restrict__ Cout, int ldc,
    const float* __restrict__ outn)
{
    __shared__ __align__(16) __nv_bfloat16 As_hi[128][40];
    __shared__ __align__(16) __nv_bfloat16 As_lo[128][40];
    __shared__ __align__(16) __nv_bfloat16 Bs_hi[32][136];
    __shared__ __align__(16) __nv_bfloat16 Bs_lo[32][136];

    const int tid = threadIdx.x;
    const int warp = tid >> 5, lane = tid & 31;
    const int row0 = blockIdx.x * 128;
    const int col0 = blockIdx.y * 128;

    // staging: A thread covers row=tid>>1, k window (tid&1)*16 (4 float4)
    const int sar = tid >> 1, sak = (tid & 1) * 16;
    // B thread covers k=tid>>3, n window (tid&7)*16 (2 uint4 each of hi/lo)
    const int sbk = tid >> 3, sbn = (tid & 7) * 16;
    const float* Ap = A + (size_t)(row0 + sar) * lda + sak;
    const __nv_bfloat16* Wph = Whi + (size_t)sbk * ldw + col0 + sbn;
    const __nv_bfloat16* Wpl = Wlo + (size_t)sbk * ldw + col0 + sbn;

    const int warpM = (warp >> 2) * 64;
    const int warpN = (warp & 3) * 32;
    const int qr = (lane & 7) + ((lane >> 3) & 1) * 8;
    const int qc = (lane >> 4) * 8;
    uint32_t aHi = (uint32_t)__cvta_generic_to_shared(&As_hi[warpM + qr][qc]);
    uint32_t aLo = (uint32_t)__cvta_generic_to_shared(&As_lo[warpM + qr][qc]);
    uint32_t bHi = (uint32_t)__cvta_generic_to_shared(&Bs_hi[qr][warpN + qc]);
    uint32_t bLo = (uint32_t)__cvta_generic_to_shared(&Bs_lo[qr][warpN + qc]);
    const uint32_t ArowB = 40 * 2;
    const uint32_t BrowB = 136 * 2;

    float acc[4][4][4] = {};

    // prologue prefetch
    float4 pa[4];
    uint4 pbh[2], pbl[2];
#pragma unroll
    for (int q = 0; q < 4; q++) pa[q] = *(const float4*)(Ap + q * 4);
    pbh[0] = ((const uint4*)Wph)[0]; pbh[1] = ((const uint4*)Wph)[1];
    pbl[0] = ((const uint4*)Wpl)[0]; pbl[1] = ((const uint4*)Wpl)[1];

    for (int k0 = 0; k0 < 256; k0 += 32) {
#pragma unroll
        for (int q = 0; q < 4; q++)
            store_hilo(&As_hi[sar][sak + q * 4], &As_lo[sar][sak + q * 4], pa[q]);
        *(uint4*)&Bs_hi[sbk][sbn]     = pbh[0];
        *(uint4*)&Bs_hi[sbk][sbn + 8] = pbh[1];
        *(uint4*)&Bs_lo[sbk][sbn]     = pbl[0];
        *(uint4*)&Bs_lo[sbk][sbn + 8] = pbl[1];
        __syncthreads();

        if (k0 + 32 < 256) {   // prefetch next slab; overlaps MMA phase
#pragma unroll
            for (int q = 0; q < 4; q++)
                pa[q] = *(const float4*)(Ap + k0 + 32 + q * 4);
            const __nv_bfloat16* bh = Wph + (size_t)(k0 + 32) * ldw;
            const __nv_bfloat16* bl = Wpl + (size_t)(k0 + 32) * ldw;
            pbh[0] = ((const uint4*)bh)[0]; pbh[1] = ((const uint4*)bh)[1];
            pbl[0] = ((const uint4*)bl)[0]; pbl[1] = ((const uint4*)bl)[1];
        }

#pragma unroll
        for (int ks = 0; ks < 2; ks++) {
            uint32_t ah[4][4], al[4][4];
#pragma unroll
            for (int i = 0; i < 4; i++) {
                uint32_t off = (uint32_t)(i * 16) * ArowB + ks * 32;
                ldsm_x4(aHi + off, ah[i][0], ah[i][1], ah[i][2], ah[i][3]);
                ldsm_x4(aLo + off, al[i][0], al[i][1], al[i][2], al[i][3]);
            }
            uint32_t bh[2][4], bl[2][4];
#pragma unroll
            for (int j2 = 0; j2 < 2; j2++) {
                uint32_t off = (uint32_t)(j2 * 16) * 2 + ks * 16 * BrowB;
                ldsm_x4_t(bHi + off, bh[j2][0], bh[j2][1], bh[j2][2], bh[j2][3]);
                ldsm_x4_t(bLo + off, bl[j2][0], bl[j2][1], bl[j2][2], bl[j2][3]);
            }
#pragma unroll
            for (int i = 0; i < 4; i++)
#pragma unroll
                for (int j = 0; j < 4; j++)
                    mma16816(acc[i][j], ah[i], bh[j >> 1][(j & 1) * 2], bh[j >> 1][(j & 1) * 2 + 1]);
#pragma unroll
            for (int i = 0; i < 4; i++)
#pragma unroll
                for (int j = 0; j < 4; j++)
                    mma16816(acc[i][j], ah[i], bl[j >> 1][(j & 1) * 2], bl[j >> 1][(j & 1) * 2 + 1]);
#pragma unroll
            for (int i = 0; i < 4; i++)
#pragma unroll
                for (int j = 0; j < 4; j++)
                    mma16816(acc[i][j], al[i], bh[j >> 1][(j & 1) * 2], bh[j >> 1][(j & 1) * 2 + 1]);
        }
        __syncthreads();
    }

    const int er = lane >> 2, ec = (lane & 3) * 2;
#pragma unroll
    for (int i = 0; i < 4; i++) {
        int r0 = row0 + warpM + i * 16 + er;
#pragma unroll
        for (int j = 0; j < 4; j++) {
            int c = col0 + warpN + j * 8 + ec;
#pragma unroll
            for (int h = 0; h < 2; h++) {
                int row = r0 + h * 8;
                float v0 = acc[i][j][h * 2], v1 = acc[i][j][h * 2 + 1];
                float2 r;
                if (EPI == 0) {
                    r.x = fsilu(v0);
                    r.y = fsilu(v1);
                } else {
                    float2 vv = *(const float2*)(A + (size_t)row * lda + c);
                    float2 oo = *(const float2*)(outn + (size_t)row * CDIM + c);
                    float2 bb = *(const float2*)(bias + c);
                    float g;
                    g = fsig(fsilu(v0 + bb.x)); r.x = g * vv.x + (1.f - g) * oo.x;
                    g = fsig(fsilu(v1 + bb.y)); r.y = g * vv.y + (1.f - g) * oo.y;
                }
                *(float2*)(Cout + (size_t)row * ldc + c) = r;
            }
        }
    }
}

// ---------------------------------------------------------------------------
// Fused per-token kernel: warps 0-7 rmsnorm+rope on q,k; warp 8 wp projection.
// ---------------------------------------------------------------------------
__global__ void __launch_bounds__(288) fused_norm_wp_kernel(
    const float* __restrict__ w_qnorm, const float* __restrict__ w_knorm,
    const float* __restrict__ x, const float* __restrict__ W_wp,
    const float* __restrict__ b_wp, float* __restrict__ wp_out)
{
    int token = blockIdx.x;
    int warpId = threadIdx.x >> 5, lane = threadIdx.x & 31;

    if (warpId < 8) {
        int which = warpId >> 2;    // 0=q, 1=k
        int head  = warpId & 3;
        const float* wn = which ? w_knorm : w_qnorm;
        float* base = g_qkv + (size_t)token * QKVN + which * CDIM + head * 64;

        float x1 = base[lane], x2 = base[lane + 32];
        float ss = x1 * x1 + x2 * x2;
#pragma unroll
        for (int off = 16; off; off >>= 1) ss += __shfl_xor_sync(0xffffffffu, ss, off);
        float inv = rsqrtf(ss * (1.f / 64.f) + 1e-6f);
        x1 = x1 * inv * wn[lane];
        x2 = x2 * inv * wn[lane + 32];

        float freq = exp2f(-(float)lane * (13.287712379549449f / 32.f));
        float ang = (float)head * freq;
        float c = cosf(ang), s = sinf(ang);
        base[lane]      = x1 * c - x2 * s;
        base[lane + 32] = x1 * s + x2 * c;
    } else {
        const float* xr = x + (size_t)token * CDIM;
        float acc[8] = {};
        for (int k = lane; k < CDIM; k += 32) {
            float xv = xr[k];
            const float* wr = W_wp + k * 8;
#pragma unroll
            for (int o = 0; o < 8; o++) acc[o] += xv * wr[o];
        }
#pragma unroll
        for (int o = 0; o < 8; o++)
#pragma unroll
            for (int off = 16; off; off >>= 1)
                acc[o] += __shfl_xor_sync(0xffffffffu, acc[o], off);
        if (lane < 8) {
            const float maxd = 4.242640687119285f;  // sqrt(18)
            float t = acc[lane] + b_wp[lane];
            float s = fsilu(t);
            float sg = fsig(s);
            wp_out[token * 8 + lane] = (lane < 4) ? (sg * maxd + 0.5f) : (sg * 9.5f + 0.5f);
        }
    }
}

// ---------------------------------------------------------------------------
// Attention body: MODE=0 interior (no bounds checks), MODE=1 border (checked).
// Single launch: blocks [0,3364) interior, [3364,4096) border.
// ---------------------------------------------------------------------------
template <int MODE>
__device__ __forceinline__ void attn_body(int blk, const float* __restrict__ w_onorm)
{
    __shared__ __align__(16) float s_q[8][64];
    __shared__ float s_p[8][52];
    __shared__ float s_out[2][256];
    __shared__ float s_ss[2];
    __shared__ float s_rinv[2];
    __shared__ int   s_tok[2];

    const int warpId = threadIdx.x >> 5, lane = threadIdx.x & 31;
    const int tl = warpId >> 2;
    const int head = warpId & 3;

    int token;
    if (MODE == 0) {
        int b = blk / 1682;                  // 58*29
        int rem = blk - b * 1682;
        int y = 3 + rem / 29;
        int x = 3 + 2 * (rem % 29) + tl;
        token = (b << 12) + (y << 6) + x;
    } else {
        int bi = blk * 2 + tl;               // < 1464
        int b = bi / 732;
        int r = bi - b * 732;
        int y, x;
        if (r < 384) { int ry = r >> 6; y = (ry < 3) ? ry : 58 + ry; x = r & 63; }
        else { int r2 = r - 384; y = 3 + r2 / 6; int xi = r2 % 6; x = (xi < 3) ? xi : 58 + xi; }
        token = (b << 12) + (y << 6) + x;
    }
    const int b = token >> 12;
    const int y = (token >> 6) & 63, xx = token & 63;

    if (threadIdx.x < 2) s_ss[threadIdx.x] = 0.f;
    if (lane == 0 && head == 0) s_tok[tl] = token;

    const float* qrow = g_qkv + (size_t)token * QKVN + head * 64;
    s_q[warpId][lane]      = qrow[lane];
    s_q[warpId][lane + 32] = qrow[lane + 32];
    __syncwarp();

    const int sub = lane & 7;
    const int grp = lane >> 3;
    float4 q4a = ((const float4*)s_q[warpId])[sub];
    float4 q4b = ((const float4*)s_q[warpId])[sub + 8];

    const float width = g_wp[token * 8 + head];
    const float sharp = g_wp[token * 8 + 4 + head];
    const float* kbase = g_qkv + 256 + (size_t)head * 64;

#pragma unroll
    for (int r = 0; r < 13; r++) {
        int w = r * 4 + grp;
        bool act = (w < 49);
        int wc = act ? w : 48;
        int di = wc / 7 - 3, dj = wc % 7 - 3;
        int ny = y + di, nx = xx + dj;
        bool inb = (MODE == 0) ? true : (((unsigned)ny < 64u) & ((unsigned)nx < 64u));
        float part = 0.f;
        if (act & inb) {
            const float4* kr = (const float4*)(kbase +
                (size_t)((b << 12) + (ny << 6) + nx) * QKVN);
            float4 ka = kr[sub];
            float4 kb = kr[sub + 8];
            part = q4a.x * ka.x + q4a.y * ka.y + q4a.z * ka.z + q4a.w * ka.w
                 + q4b.x * kb.x + q4b.y * kb.y + q4b.z * kb.z + q4b.w * kb.w;
        }
        part += __shfl_xor_sync(0xffffffffu, part, 1);
        part += __shfl_xor_sync(0xffffffffu, part, 2);
        part += __shfl_xor_sync(0xffffffffu, part, 4);
        if (act && sub == 0) {
            float rd = sqrtf((float)(di * di + dj * dj));
            float mask = fsig((width - rd) * sharp);
            s_p[warpId][w] = part * 0.125f - (1.f - mask) * 10000.f;
        }
    }
    __syncwarp();

    float sc0 = s_p[warpId][lane];
    float sc1 = (lane + 32 < 49) ? s_p[warpId][lane + 32] : -1e30f;
    float mx = fmaxf(sc0, sc1);
#pragma unroll
    for (int off = 16; off; off >>= 1) mx = fmaxf(mx, __shfl_xor_sync(0xffffffffu, mx, off));
    float p0 = __expf(sc0 - mx);
    float p1 = __expf(sc1 - mx);
    float ds = p0 + p1;
#pragma unroll
    for (int off = 16; off; off >>= 1) ds += __shfl_xor_sync(0xffffffffu, ds, off);
    float rdm = 1.f / ds;
    s_p[warpId][lane] = p0 * rdm;
    if (lane + 32 < 49) s_p[warpId][lane + 32] = p1 * rdm;
    __syncwarp();

    float o0 = 0.f, o1 = 0.f;
    const float* vtok = g_qkv + (size_t)token * QKVN + 512 + head * 64;
#pragma unroll
    for (int ii = 0; ii < 7; ii++) {
        int ny = y + ii - 3;
        if (MODE == 1 && (unsigned)ny >= 64u) continue;
#pragma unroll
        for (int jj = 0; jj < 7; jj++) {
            int nx = xx + jj - 3;
            if (MODE == 1 && (unsigned)nx >= 64u) continue;
            float p = s_p[warpId][ii * 7 + jj];
            const float* vrow = vtok + (ptrdiff_t)((ii - 3) * 64 + (jj - 3)) * QKVN;
            o0 += p * vrow[lane];
            o1 += p * vrow[lane + 32];
        }
    }

    s_out[tl][head * 64 + lane]      = o0;
    s_out[tl][head * 64 + lane + 32] = o1;

    float pss = o0 * o0 + o1 * o1;
#pragma unroll
    for (int off = 16; off; off >>= 1) pss += __shfl_xor_sync(0xffffffffu, pss, off);
    __syncthreads();
    if (lane == 0) atomicAdd(&s_ss[tl], pss);
    __syncthreads();
    if (threadIdx.x < 2)
        s_rinv[threadIdx.x] = rsqrtf(s_ss[threadIdx.x] * (1.f / 256.f) + 1e-6f);
    __syncthreads();

    for (int e = threadIdx.x; e < 512; e += 256) {
        int t2 = e >> 8, c = e & 255;
        g_outn[(size_t)s_tok[t2] * CDIM + c] = s_out[t2][c] * s_rinv[t2] * w_onorm[c];
    }
}

__global__ void __launch_bounds__(256) attn_all(const float* __restrict__ w_onorm)
{
    if (blockIdx.x < 3364) attn_body<0>(blockIdx.x, w_onorm);
    else                   attn_body<1>(blockIdx.x - 3364, w_onorm);
}

// ---------------------------------------------------------------------------
extern "C" void kernel_launch(void* const* d_in, const int* in_sizes, int n_in,
                              void* d_out, int out_size)
{
    const float* x       = (const float*)d_in[0];
    const float* W_qkv   = (const float*)d_in[1];
    const float* w_qnorm = (const float*)d_in[2];
    const float* w_knorm = (const float*)d_in[3];
    const float* W_wp    = (const float*)d_in[4];
    const float* b_wp    = (const float*)d_in[5];
    const float* w_onorm = (const float*)d_in[6];
    const float* W_out   = (const float*)d_in[7];
    const float* W_gate  = (const float*)d_in[8];
    const float* b_gate  = (const float*)d_in[9];
    float* out = (float*)d_out;

    float *p_qkv, *p_wp, *p_outn, *p_merged;
    cudaGetSymbolAddress((void**)&p_qkv, g_qkv);
    cudaGetSymbolAddress((void**)&p_wp, g_wp);
    cudaGetSymbolAddress((void**)&p_outn, g_outn);
    cudaGetSymbolAddress((void**)&p_merged, g_merged);
    __nv_bfloat16 *p_wqh, *p_wql, *p_wgh, *p_wgl, *p_woh, *p_wol;
    cudaGetSymbolAddress((void**)&p_wqh, g_wq_hi); cudaGetSymbolAddress((void**)&p_wql, g_wq_lo);
    cudaGetSymbolAddress((void**)&p_wgh, g_wg_hi); cudaGetSymbolAddress((void**)&p_wgl, g_wg_lo);
    cudaGetSymbolAddress((void**)&p_woh, g_wo_hi); cudaGetSymbolAddress((void**)&p_wol, g_wo_lo);

    // 0. preconvert weights to bf16 hi/lo (~459K elems)
    const int NW = CDIM * QKVN + 2 * CDIM * CDIM;
    prep_w_kernel<<<(NW + 255) / 256, 256>>>(W_qkv, W_gate, W_out);

    // 1. qkv = silu(x @ W_qkv)
    gemm_bf16s<0><<<dim3(NTOK / 128, QKVN / 128), 256>>>(
        x, CDIM, p_wqh, p_wql, QKVN, nullptr, p_qkv, QKVN, nullptr);
    // 2. fused rmsnorm+rope + wp projection
    fused_norm_wp_kernel<<<NTOK, 288>>>(w_qnorm, w_knorm, x, W_wp, b_wp, p_wp);
    // 3. windowed attention + fused output rmsnorm (one launch)
    attn_all<<<4096, 256>>>(w_onorm);
    // 4. gate GEMM + merge epilogue: merged = gate*v + (1-gate)*outn
    gemm_bf16s<1><<<dim3(NTOK / 128, CDIM / 128), 256>>>(
        p_qkv + 512, QKVN, p_wgh, p_wgl, CDIM, b_gate, p_merged, CDIM, p_outn);
    // 5. final: silu(merged @ W_out)
    gemm_bf16s<0><<<dim3(NTOK / 128, CDIM / 128), 256>>>(
        p_merged, CDIM, p_woh, p_wol, CDIM, nullptr, out, CDIM, nullptr);
}